// round 2
// baseline (speedup 1.0000x reference)
#include <cuda_runtime.h>
#include <cuda_bf16.h>
#include <math.h>

#define Bd   8
#define Hd   1024
#define Ld   2048
#define Cd   2
#define NF   4096      // FFT length = 2L
#define CH   2048      // C*H (GEMM K)
#define OUTD 2048      // 2H  (GEMM M)

// ---------------- scratch (static device globals; no runtime allocation) ----
__device__ float2 d_kf[(size_t)CH * NF];      // kernel spectra, 64 MB
__device__ int    d_kf_nz[CH];                // per-row nonzero flags
__device__ float  d_g[(size_t)Bd * CH * Ld];  // post-GELU activations, 134 MB
__device__ float  d_z[(size_t)Bd * OUTD * Ld];// pre-GLU linear output, 134 MB

__device__ __forceinline__ float2 cmulf(float2 a, float2 b) {
    return make_float2(a.x * b.x - a.y * b.y, a.x * b.y + a.y * b.x);
}

// ---------------------------------------------------------------------------
// Stockham radix-2 FFT, N=4096, 256 threads/block, self-sorting ping-pong.
// SIGN = -1 forward (e^{-i...}), +1 inverse (unscaled). Result ends in 'a'
// (12 stages = even number of swaps). Ends with __syncthreads().
// ---------------------------------------------------------------------------
template<int SIGN>
__device__ void fft4096(float2* a, float2* b) {
    float2 *s = a, *d = b;
    int Ns = 1;
    #pragma unroll 1
    for (int stage = 0; stage < 12; ++stage) {
        __syncthreads();
        float wstep = (float)SIGN * 3.14159265358979323846f / (float)Ns;
        #pragma unroll
        for (int it = 0; it < 8; ++it) {
            int j = threadIdx.x + (it << 8);          // 0..2047
            float2 v0 = s[j];
            float2 v1 = s[j + 2048];
            int jm = j & (Ns - 1);                    // j mod Ns
            float ang = wstep * (float)jm;            // |ang| < pi
            float sn, cs;
            __sincosf(ang, &sn, &cs);
            float2 t = make_float2(cs * v1.x - sn * v1.y,
                                   cs * v1.y + sn * v1.x);
            int idxD = 2 * j - jm;                    // (j/Ns)*2Ns + jm
            d[idxD]      = make_float2(v0.x + t.x, v0.y + t.y);
            d[idxD + Ns] = make_float2(v0.x - t.x, v0.y - t.y);
        }
        float2* tmp = s; s = d; d = tmp;
        Ns <<= 1;
    }
    __syncthreads();
}

// ---------------------------------------------------------------------------
// Kernel 1: soft-threshold the filter, detect all-zero rows, FFT nonzero rows.
// One block per (c,h) row. smem = 2 * 4096 * float2 = 64 KB.
// ---------------------------------------------------------------------------
__global__ void kf_kernel(const float* __restrict__ kern) {
    extern __shared__ float2 sm[];
    float2* A  = sm;
    float2* Bf = sm + NF;
    int row = blockIdx.x;                       // c*H + h
    const float* kr = kern + (size_t)row * NF;
    int any = 0;
    for (int i = threadIdx.x; i < NF; i += 256) {
        float v = kr[i];
        float t = fmaxf(fabsf(v) - 0.1f, 0.0f); // soft threshold, lam = 0.1
        t = copysignf(t, v);
        any |= (t != 0.0f);
        A[i] = make_float2(t, 0.0f);
    }
    int any_nz = __syncthreads_or(any);
    if (!any_nz) {
        if (threadIdx.x == 0) d_kf_nz[row] = 0;
        return;                                 // spectrum is exactly zero
    }
    fft4096<-1>(A, Bf);
    float2* out = d_kf + (size_t)row * NF;
    for (int i = threadIdx.x; i < NF; i += 256) out[i] = A[i];
    if (threadIdx.x == 0) d_kf_nz[row] = 1;
}

// ---------------------------------------------------------------------------
// Kernel 2: per (b,h): forward FFT of u (if any filter row nonzero), then per
// c: spectral multiply + inverse FFT, add D bypass, GELU, store g[b][c*H+h][l].
// Zero filter rows collapse to y = u * D exactly.
// One block per (b,h). smem = 3 * 4096 * float2 = 96 KB.
// ---------------------------------------------------------------------------
__global__ void conv_kernel(const float* __restrict__ u,
                            const float* __restrict__ Dp) {
    extern __shared__ float2 sm[];
    float2* A  = sm;
    float2* Bf = sm + NF;
    float2* Uf = sm + 2 * NF;
    int b = blockIdx.x >> 10;
    int h = blockIdx.x & (Hd - 1);
    const float* ur = u + ((size_t)b * Hd + h) * Ld;
    float ul[8];
    #pragma unroll
    for (int it = 0; it < 8; ++it) {
        int l = threadIdx.x + (it << 8);
        float v = ur[l];
        ul[it] = v;
        A[l]      = make_float2(v, 0.0f);
        A[l + Ld] = make_float2(0.0f, 0.0f);    // zero-pad to 4096
    }
    int nz0 = d_kf_nz[h];
    int nz1 = d_kf_nz[Hd + h];
    if (nz0 | nz1) {                            // uniform across block
        fft4096<-1>(A, Bf);
        for (int i = threadIdx.x; i < NF; i += 256) Uf[i] = A[i];
        __syncthreads();
    }
    #pragma unroll 1
    for (int c = 0; c < Cd; ++c) {
        int nz = c ? nz1 : nz0;                 // uniform across block
        float Dch = Dp[c * Hd + h];
        float* gr = d_g + ((size_t)b * CH + (size_t)c * Hd + h) * Ld;
        if (nz) {
            __syncthreads();
            const float2* kfr = d_kf + ((size_t)c * Hd + h) * NF;
            for (int i = threadIdx.x; i < NF; i += 256)
                A[i] = cmulf(Uf[i], kfr[i]);
            fft4096<1>(A, Bf);
            #pragma unroll
            for (int it = 0; it < 8; ++it) {
                int l = threadIdx.x + (it << 8);
                float y = A[l].x * (1.0f / (float)NF) + ul[it] * Dch;
                float ge = 0.5f * y * (1.0f + erff(y * 0.70710678118654752f));
                gr[l] = ge;
            }
        } else {                                // conv contribution == 0
            #pragma unroll
            for (int it = 0; it < 8; ++it) {
                int l = threadIdx.x + (it << 8);
                float y = ul[it] * Dch;
                float ge = 0.5f * y * (1.0f + erff(y * 0.70710678118654752f));
                gr[l] = ge;
            }
        }
    }
}

// ---------------------------------------------------------------------------
// Kernel 3: fp32 GEMM  z[b][o][l] = sum_k W[o][k] * g[b][k][l] + bias[o]
// Block tile 128(o) x 64(l), 256 threads, 8x4 micro-tile, K-chunks of 16.
// ---------------------------------------------------------------------------
__global__ void gemm_kernel(const float* __restrict__ W,
                            const float* __restrict__ bias) {
    __shared__ float As[16][129];               // [kk][o], padded vs conflicts
    __shared__ float Bs[16][64];                // [kk][l]
    int b  = blockIdx.z;
    int o0 = blockIdx.y * 128;
    int l0 = blockIdx.x * 64;
    int tid = threadIdx.x;
    int tx = tid & 15, ty = tid >> 4;
    const float* gb = d_g + (size_t)b * CH * Ld;

    float acc[8][4];
    #pragma unroll
    for (int i = 0; i < 8; ++i)
        #pragma unroll
        for (int j = 0; j < 4; ++j) acc[i][j] = 0.0f;

    for (int k0 = 0; k0 < CH; k0 += 16) {
        {   // load W tile: 128 x 16
            int kk = tid & 15;
            int ob = tid >> 4;
            #pragma unroll
            for (int r = 0; r < 8; ++r) {
                int o = ob + r * 16;
                As[kk][o] = W[(size_t)(o0 + o) * CH + k0 + kk];
            }
        }
        {   // load g tile: 16 x 64
            int ll = tid & 63;
            int kb = tid >> 6;
            #pragma unroll
            for (int r = 0; r < 4; ++r) {
                int kk = kb + r * 4;
                Bs[kk][ll] = gb[(size_t)(k0 + kk) * Ld + l0 + ll];
            }
        }
        __syncthreads();
        #pragma unroll
        for (int kk = 0; kk < 16; ++kk) {
            float av[8], bv[4];
            #pragma unroll
            for (int i = 0; i < 8; ++i) av[i] = As[kk][ty + 16 * i];
            #pragma unroll
            for (int j = 0; j < 4; ++j) bv[j] = Bs[kk][tx + 16 * j];
            #pragma unroll
            for (int i = 0; i < 8; ++i)
                #pragma unroll
                for (int j = 0; j < 4; ++j)
                    acc[i][j] = fmaf(av[i], bv[j], acc[i][j]);
        }
        __syncthreads();
    }
    float* zb = d_z + (size_t)b * OUTD * Ld;
    #pragma unroll
    for (int i = 0; i < 8; ++i) {
        int o = o0 + ty + 16 * i;
        float bo = bias[o];
        #pragma unroll
        for (int j = 0; j < 4; ++j) {
            int l = l0 + tx + 16 * j;
            zb[(size_t)o * Ld + l] = acc[i][j] + bo;
        }
    }
}

// ---------------------------------------------------------------------------
// Kernel 4: GLU + final transpose-free write: out[b][h][l] =
//           z[b][h][l] * sigmoid(z[b][h+H][l])
// ---------------------------------------------------------------------------
__global__ void glu_kernel(float* __restrict__ out) {
    int idx = blockIdx.x * blockDim.x + threadIdx.x;  // over B*H*L = 2^24
    if (idx >= Bd * Hd * Ld) return;
    int l = idx & (Ld - 1);
    int h = (idx >> 11) & (Hd - 1);
    int b = idx >> 21;
    const float* zb = d_z + (size_t)b * OUTD * Ld;
    float a = zb[(size_t)h * Ld + l];
    float g = zb[(size_t)(h + Hd) * Ld + l];
    out[idx] = a * (1.0f / (1.0f + expf(-g)));
}

// ---------------------------------------------------------------------------
extern "C" void kernel_launch(void* const* d_in, const int* in_sizes, int n_in,
                              void* d_out, int out_size) {
    const float* u    = (const float*)d_in[0];   // (B,H,L)
    const float* kern = (const float*)d_in[1];   // (C,H,2L)
    const float* D    = (const float*)d_in[2];   // (C,H)
    const float* Wout = (const float*)d_in[3];   // (2H, C*H)
    const float* bout = (const float*)d_in[4];   // (2H,)
    float* out = (float*)d_out;                  // (B,H,L)

    cudaFuncSetAttribute(kf_kernel,
        cudaFuncAttributeMaxDynamicSharedMemorySize, 2 * NF * (int)sizeof(float2));
    cudaFuncSetAttribute(conv_kernel,
        cudaFuncAttributeMaxDynamicSharedMemorySize, 3 * NF * (int)sizeof(float2));

    kf_kernel<<<CH, 256, 2 * NF * sizeof(float2)>>>(kern);
    conv_kernel<<<Bd * Hd, 256, 3 * NF * sizeof(float2)>>>(u, D);
    gemm_kernel<<<dim3(Ld / 64, OUTD / 128, Bd), 256>>>(Wout, bout);
    glu_kernel<<<(Bd * Hd * Ld + 255) / 256, 256>>>(out);
}

// round 4
// speedup vs baseline: 7.2208x; 7.2208x over previous
#include <cuda_runtime.h>
#include <cuda_bf16.h>
#include <cuda_fp16.h>
#include <math.h>
#include <stdint.h>

#define Bd   8
#define Hd   1024
#define Ld   2048
#define Cd   2
#define NF   4096      // FFT length = 2L
#define CH   2048      // C*H (GEMM K)
#define OUTD 2048      // 2H  (GEMM M)

// ---------------- scratch (static device globals; no runtime allocation) ----
__device__ float2 d_kf[(size_t)CH * NF];            // kernel spectra
__device__ int    d_kf_nz[CH];                      // per-row nonzero flags
__device__ float  d_g[(size_t)Bd * CH * Ld];        // post-GELU activations (k-major)
__device__ float  d_z[(size_t)Bd * OUTD * Ld];      // pre-GLU linear output
__device__ __half d_W_h[(size_t)OUTD * CH];         // W fp16 (K-major)
__device__ __half d_gt[(size_t)Bd * Ld * CH];       // g^T fp16 (l-major, k contig)

__device__ __forceinline__ float2 cmulf(float2 a, float2 b) {
    return make_float2(a.x * b.x - a.y * b.y, a.x * b.y + a.y * b.x);
}

// ---------------------------------------------------------------------------
// Stockham radix-2 FFT, N=4096, 256 threads/block.
// ---------------------------------------------------------------------------
template<int SIGN>
__device__ void fft4096(float2* a, float2* b) {
    float2 *s = a, *d = b;
    int Ns = 1;
    #pragma unroll 1
    for (int stage = 0; stage < 12; ++stage) {
        __syncthreads();
        float wstep = (float)SIGN * 3.14159265358979323846f / (float)Ns;
        #pragma unroll
        for (int it = 0; it < 8; ++it) {
            int j = threadIdx.x + (it << 8);
            float2 v0 = s[j];
            float2 v1 = s[j + 2048];
            int jm = j & (Ns - 1);
            float ang = wstep * (float)jm;
            float sn, cs;
            __sincosf(ang, &sn, &cs);
            float2 t = make_float2(cs * v1.x - sn * v1.y,
                                   cs * v1.y + sn * v1.x);
            int idxD = 2 * j - jm;
            d[idxD]      = make_float2(v0.x + t.x, v0.y + t.y);
            d[idxD + Ns] = make_float2(v0.x - t.x, v0.y - t.y);
        }
        float2* tmp = s; s = d; d = tmp;
        Ns <<= 1;
    }
    __syncthreads();
}

// ---------------------------------------------------------------------------
// Kernel 1: soft-threshold filter rows, FFT nonzero rows.
// ---------------------------------------------------------------------------
__global__ void kf_kernel(const float* __restrict__ kern) {
    extern __shared__ float2 sm[];
    float2* A  = sm;
    float2* Bf = sm + NF;
    int row = blockIdx.x;
    const float* kr = kern + (size_t)row * NF;
    int any = 0;
    for (int i = threadIdx.x; i < NF; i += 256) {
        float v = kr[i];
        float t = fmaxf(fabsf(v) - 0.1f, 0.0f);
        t = copysignf(t, v);
        any |= (t != 0.0f);
        A[i] = make_float2(t, 0.0f);
    }
    int any_nz = __syncthreads_or(any);
    if (!any_nz) {
        if (threadIdx.x == 0) d_kf_nz[row] = 0;
        return;
    }
    fft4096<-1>(A, Bf);
    float2* out = d_kf + (size_t)row * NF;
    for (int i = threadIdx.x; i < NF; i += 256) out[i] = A[i];
    if (threadIdx.x == 0) d_kf_nz[row] = 1;
}

// ---------------------------------------------------------------------------
// Kernel 2: FFT conv (+ collapse for zero rows) + D bypass + GELU -> d_g
// ---------------------------------------------------------------------------
__global__ void conv_kernel(const float* __restrict__ u,
                            const float* __restrict__ Dp) {
    extern __shared__ float2 sm[];
    float2* A  = sm;
    float2* Bf = sm + NF;
    float2* Uf = sm + 2 * NF;
    int b = blockIdx.x >> 10;
    int h = blockIdx.x & (Hd - 1);
    const float* ur = u + ((size_t)b * Hd + h) * Ld;
    float ul[8];
    #pragma unroll
    for (int it = 0; it < 8; ++it) {
        int l = threadIdx.x + (it << 8);
        float v = ur[l];
        ul[it] = v;
        A[l]      = make_float2(v, 0.0f);
        A[l + Ld] = make_float2(0.0f, 0.0f);
    }
    int nz0 = d_kf_nz[h];
    int nz1 = d_kf_nz[Hd + h];
    if (nz0 | nz1) {
        fft4096<-1>(A, Bf);
        for (int i = threadIdx.x; i < NF; i += 256) Uf[i] = A[i];
        __syncthreads();
    }
    #pragma unroll 1
    for (int c = 0; c < Cd; ++c) {
        int nz = c ? nz1 : nz0;
        float Dch = Dp[c * Hd + h];
        float* gr = d_g + ((size_t)b * CH + (size_t)c * Hd + h) * Ld;
        if (nz) {
            __syncthreads();
            const float2* kfr = d_kf + ((size_t)c * Hd + h) * NF;
            for (int i = threadIdx.x; i < NF; i += 256)
                A[i] = cmulf(Uf[i], kfr[i]);
            fft4096<1>(A, Bf);
            #pragma unroll
            for (int it = 0; it < 8; ++it) {
                int l = threadIdx.x + (it << 8);
                float y = A[l].x * (1.0f / (float)NF) + ul[it] * Dch;
                gr[l] = 0.5f * y * (1.0f + erff(y * 0.70710678118654752f));
            }
        } else {
            #pragma unroll
            for (int it = 0; it < 8; ++it) {
                int l = threadIdx.x + (it << 8);
                float y = ul[it] * Dch;
                gr[l] = 0.5f * y * (1.0f + erff(y * 0.70710678118654752f));
            }
        }
    }
}

// ---------------------------------------------------------------------------
// Kernel 3: W fp32 -> fp16 (layout unchanged: K-major rows).
// ---------------------------------------------------------------------------
__global__ void whalf_kernel(const float* __restrict__ W) {
    int idx = blockIdx.x * blockDim.x + threadIdx.x;
    if (idx >= OUTD * CH) return;
    d_W_h[idx] = __float2half(W[idx]);
}

// ---------------------------------------------------------------------------
// Kernel 4: transpose g[b][k][l] fp32 -> gt[b][l][k] fp16.
// ---------------------------------------------------------------------------
__global__ void transp_kernel() {
    __shared__ float t[32][33];
    int b  = blockIdx.z;
    int k0 = blockIdx.y * 32;
    int l0 = blockIdx.x * 32;
    int tx = threadIdx.x, ty = threadIdx.y;
    const float* gb = d_g + (size_t)b * CH * Ld;
    #pragma unroll
    for (int r = 0; r < 4; ++r) {
        int k = k0 + ty + r * 8;
        t[ty + r * 8][tx] = gb[(size_t)k * Ld + l0 + tx];
    }
    __syncthreads();
    size_t obase = ((size_t)b * Ld) * CH;
    #pragma unroll
    for (int r = 0; r < 4; ++r) {
        int l = l0 + ty + r * 8;
        d_gt[obase + (size_t)l * CH + k0 + tx] = __float2half(t[tx][ty + r * 8]);
    }
}

// ---------------------------------------------------------------------------
// HMMA GEMM helpers
// ---------------------------------------------------------------------------
__device__ __forceinline__ uint32_t smem_u32(const void* p) {
    uint32_t a;
    asm("{ .reg .u64 t; cvta.to.shared.u64 t, %1; cvt.u32.u64 %0, t; }"
        : "=r"(a) : "l"(p));
    return a;
}
#define SWZ128(x) ((x) ^ (((x) >> 3) & 0x70))
__device__ __forceinline__ void cp16(uint32_t dst, const void* src) {
    asm volatile("cp.async.cg.shared.global [%0], [%1], 16;"
                 :: "r"(dst), "l"(src) : "memory");
}
__device__ __forceinline__ void ldsm4(uint32_t* r, uint32_t addr) {
    asm volatile("ldmatrix.sync.aligned.m8n8.x4.shared.b16 {%0,%1,%2,%3}, [%4];"
                 : "=r"(r[0]), "=r"(r[1]), "=r"(r[2]), "=r"(r[3]) : "r"(addr));
}
__device__ __forceinline__ void mma16816(float* c, const uint32_t* a,
                                         uint32_t b0, uint32_t b1) {
    asm volatile(
        "mma.sync.aligned.m16n8k16.row.col.f32.f16.f16.f32 "
        "{%0,%1,%2,%3}, {%4,%5,%6,%7}, {%8,%9}, {%0,%1,%2,%3};"
        : "+f"(c[0]), "+f"(c[1]), "+f"(c[2]), "+f"(c[3])
        : "r"(a[0]), "r"(a[1]), "r"(a[2]), "r"(a[3]), "r"(b0), "r"(b1));
}

#define STAGE_B  49152                 // A: 16KB, B: 32KB
#define GEMM_SMEM (2 * STAGE_B)

// One stage = K chunk of 64: A 128rows x 128B, B 256rows x 128B, SW128 swizzle.
__device__ __forceinline__ void load_stage_h(uint32_t base, int kc, int tid,
                                             const __half* Ap, const __half* Bp) {
    int k0 = kc * 64;
    #pragma unroll
    for (int i = 0; i < 4; ++i) {          // A: 1024 x 16B
        int c = tid + (i << 8);
        int row = c >> 3, col = c & 7;
        cp16(base + SWZ128(row * 128 + col * 16),
             Ap + (size_t)row * CH + k0 + col * 8);
    }
    #pragma unroll
    for (int i = 0; i < 8; ++i) {          // B: 2048 x 16B
        int c = tid + (i << 8);
        int row = c >> 3, col = c & 7;
        cp16(base + 16384 + SWZ128(row * 128 + col * 16),
             Bp + (size_t)row * CH + k0 + col * 8);
    }
    asm volatile("cp.async.commit_group;" ::: "memory");
}

// ---------------------------------------------------------------------------
// Kernel 5: fp16 HMMA GEMM  z[b][o][l] = sum_k W[o][k]*g[k][l] + bias[o]
// Block tile 128(o) x 256(l), warp tile 64x64, K stages of 64, double buffer.
// ---------------------------------------------------------------------------
__global__ void __launch_bounds__(256, 1) gemm_hmma(const float* __restrict__ bias) {
    extern __shared__ char smem[];
    uint32_t sb = smem_u32(smem);
    const int tid = threadIdx.x, lane = tid & 31, wid = tid >> 5;
    const int b  = blockIdx.z;
    const int o0 = blockIdx.y * 128;
    const int l0 = blockIdx.x * 256;
    const int wm = (wid >> 2) * 64;        // warp m offset within tile
    const int wn = (wid & 3) * 64;         // warp n offset within tile

    const __half* Ap = d_W_h + (size_t)o0 * CH;
    const __half* Bp = d_gt + ((size_t)b * Ld + l0) * CH;

    float acc[4][8][4];
    #pragma unroll
    for (int mi = 0; mi < 4; ++mi)
        #pragma unroll
        for (int ni = 0; ni < 8; ++ni)
            #pragma unroll
            for (int v = 0; v < 4; ++v) acc[mi][ni][v] = 0.0f;

    load_stage_h(sb, 0, tid, Ap, Bp);
    load_stage_h(sb + STAGE_B, 1, tid, Ap, Bp);

    // precomputed intra-thread ldmatrix address components
    const int arow = (lane & 15);
    const int acol = (lane >> 4) << 4;
    const int brow = (lane & 7) + ((lane & 16) >> 1);
    const int bcol = (lane & 8) << 1;

    #pragma unroll 1
    for (int kc = 0; kc < 32; ++kc) {
        uint32_t base = sb + (kc & 1) * STAGE_B;
        if (kc < 30) asm volatile("cp.async.wait_group 1;" ::: "memory");
        else         asm volatile("cp.async.wait_group 0;" ::: "memory");
        __syncthreads();
        #pragma unroll
        for (int ks = 0; ks < 4; ++ks) {
            uint32_t a[4][4], bf[4][4];
            #pragma unroll
            for (int mi = 0; mi < 4; ++mi)
                ldsm4(a[mi], base + SWZ128((wm + mi * 16 + arow) * 128 +
                                           ks * 32 + acol));
            #pragma unroll
            for (int nj = 0; nj < 4; ++nj)
                ldsm4(bf[nj], base + 16384 + SWZ128((wn + nj * 16 + brow) * 128 +
                                                    ks * 32 + bcol));
            #pragma unroll
            for (int mi = 0; mi < 4; ++mi)
                #pragma unroll
                for (int ni = 0; ni < 8; ++ni)
                    mma16816(acc[mi][ni], a[mi],
                             bf[ni >> 1][(ni & 1) * 2],
                             bf[ni >> 1][(ni & 1) * 2 + 1]);
        }
        __syncthreads();
        if (kc + 2 < 32)
            load_stage_h(base, kc + 2, tid, Ap, Bp);
    }

    // epilogue: acc -> d_z (+bias)
    #pragma unroll
    for (int mi = 0; mi < 4; ++mi) {
        int orow = o0 + wm + mi * 16 + (lane >> 2);
        float b0v = bias[orow];
        float b1v = bias[orow + 8];
        float* z0 = d_z + ((size_t)b * OUTD + orow) * Ld + l0 + wn;
        float* z1 = z0 + (size_t)8 * Ld;
        #pragma unroll
        for (int ni = 0; ni < 8; ++ni) {
            int lc = ni * 8 + (lane & 3) * 2;
            float2 v0 = make_float2(acc[mi][ni][0] + b0v, acc[mi][ni][1] + b0v);
            float2 v1 = make_float2(acc[mi][ni][2] + b1v, acc[mi][ni][3] + b1v);
            *reinterpret_cast<float2*>(z0 + lc) = v0;
            *reinterpret_cast<float2*>(z1 + lc) = v1;
        }
    }
}

// ---------------------------------------------------------------------------
// Kernel 6: GLU
// ---------------------------------------------------------------------------
__global__ void glu_kernel(float* __restrict__ out) {
    int idx = blockIdx.x * blockDim.x + threadIdx.x;
    if (idx >= Bd * Hd * Ld) return;
    int l = idx & (Ld - 1);
    int h = (idx >> 11) & (Hd - 1);
    int b = idx >> 21;
    const float* zb = d_z + (size_t)b * OUTD * Ld;
    float a = zb[(size_t)h * Ld + l];
    float g = zb[(size_t)(h + Hd) * Ld + l];
    out[idx] = a * (1.0f / (1.0f + expf(-g)));
}

// ---------------------------------------------------------------------------
extern "C" void kernel_launch(void* const* d_in, const int* in_sizes, int n_in,
                              void* d_out, int out_size) {
    const float* u    = (const float*)d_in[0];
    const float* kern = (const float*)d_in[1];
    const float* D    = (const float*)d_in[2];
    const float* Wout = (const float*)d_in[3];
    const float* bout = (const float*)d_in[4];
    float* out = (float*)d_out;

    cudaFuncSetAttribute(kf_kernel,
        cudaFuncAttributeMaxDynamicSharedMemorySize, 2 * NF * (int)sizeof(float2));
    cudaFuncSetAttribute(conv_kernel,
        cudaFuncAttributeMaxDynamicSharedMemorySize, 3 * NF * (int)sizeof(float2));
    cudaFuncSetAttribute(gemm_hmma,
        cudaFuncAttributeMaxDynamicSharedMemorySize, GEMM_SMEM);

    kf_kernel<<<CH, 256, 2 * NF * sizeof(float2)>>>(kern);
    conv_kernel<<<Bd * Hd, 256, 3 * NF * sizeof(float2)>>>(u, D);
    whalf_kernel<<<(OUTD * CH + 255) / 256, 256>>>(Wout);
    transp_kernel<<<dim3(Ld / 32, CH / 32, Bd), dim3(32, 8)>>>();
    gemm_hmma<<<dim3(Ld / 256, OUTD / 128, Bd), 256, GEMM_SMEM>>>(bout);
    glu_kernel<<<(Bd * Hd * Ld + 255) / 256, 256>>>(out);
}

// round 5
// speedup vs baseline: 8.5171x; 1.1795x over previous
#include <cuda_runtime.h>
#include <cuda_bf16.h>
#include <cuda_fp16.h>
#include <math.h>
#include <stdint.h>

#define Bd   8
#define Hd   1024
#define Ld   2048
#define Cd   2
#define NF   4096      // FFT length = 2L
#define CH   2048      // C*H (GEMM K)
#define OUTD 2048      // 2H  (GEMM M, interleaved a/g rows)

// ---------------- scratch (static device globals; no runtime allocation) ----
__device__ float2 d_kf[(size_t)CH * NF];            // kernel spectra
__device__ int    d_kf_nz[CH];                      // per-row nonzero flags
__device__ __half d_g_h[(size_t)Bd * CH * Ld];      // post-GELU activations fp16 (k-major)
__device__ __half d_W_h[(size_t)OUTD * CH];         // W fp16, rows permuted for fused GLU

__device__ __forceinline__ float2 cmulf(float2 a, float2 b) {
    return make_float2(a.x * b.x - a.y * b.y, a.x * b.y + a.y * b.x);
}

// ---------------------------------------------------------------------------
// Stockham radix-2 FFT, N=4096, 256 threads/block.
// ---------------------------------------------------------------------------
template<int SIGN>
__device__ void fft4096(float2* a, float2* b) {
    float2 *s = a, *d = b;
    int Ns = 1;
    #pragma unroll 1
    for (int stage = 0; stage < 12; ++stage) {
        __syncthreads();
        float wstep = (float)SIGN * 3.14159265358979323846f / (float)Ns;
        #pragma unroll
        for (int it = 0; it < 8; ++it) {
            int j = threadIdx.x + (it << 8);
            float2 v0 = s[j];
            float2 v1 = s[j + 2048];
            int jm = j & (Ns - 1);
            float ang = wstep * (float)jm;
            float sn, cs;
            __sincosf(ang, &sn, &cs);
            float2 t = make_float2(cs * v1.x - sn * v1.y,
                                   cs * v1.y + sn * v1.x);
            int idxD = 2 * j - jm;
            d[idxD]      = make_float2(v0.x + t.x, v0.y + t.y);
            d[idxD + Ns] = make_float2(v0.x - t.x, v0.y - t.y);
        }
        float2* tmp = s; s = d; d = tmp;
        Ns <<= 1;
    }
    __syncthreads();
}

// ---------------------------------------------------------------------------
// Kernel 1: soft-threshold filter rows, FFT nonzero rows.
// ---------------------------------------------------------------------------
__global__ void kf_kernel(const float* __restrict__ kern) {
    extern __shared__ float2 sm[];
    float2* A  = sm;
    float2* Bf = sm + NF;
    int row = blockIdx.x;
    const float* kr = kern + (size_t)row * NF;
    int any = 0;
    for (int i = threadIdx.x; i < NF; i += 256) {
        float v = kr[i];
        float t = fmaxf(fabsf(v) - 0.1f, 0.0f);
        t = copysignf(t, v);
        any |= (t != 0.0f);
        A[i] = make_float2(t, 0.0f);
    }
    int any_nz = __syncthreads_or(any);
    if (!any_nz) {
        if (threadIdx.x == 0) d_kf_nz[row] = 0;
        return;
    }
    fft4096<-1>(A, Bf);
    float2* out = d_kf + (size_t)row * NF;
    for (int i = threadIdx.x; i < NF; i += 256) out[i] = A[i];
    if (threadIdx.x == 0) d_kf_nz[row] = 1;
}

// ---------------------------------------------------------------------------
// Kernel 2: FFT conv (+ collapse for zero rows) + D bypass + GELU -> fp16 d_g_h
// Staged through smem for vectorized 16B stores.
// ---------------------------------------------------------------------------
__global__ void conv_kernel(const float* __restrict__ u,
                            const float* __restrict__ Dp) {
    extern __shared__ float2 sm[];
    float2* A  = sm;
    float2* Bf = sm + NF;
    float2* Uf = sm + 2 * NF;
    __half* stg = reinterpret_cast<__half*>(Bf);   // reuse scratch as fp16 staging
    int b = blockIdx.x >> 10;
    int h = blockIdx.x & (Hd - 1);
    const float* ur = u + ((size_t)b * Hd + h) * Ld;
    float ul[8];
    #pragma unroll
    for (int it = 0; it < 8; ++it) {
        int l = threadIdx.x + (it << 8);
        float v = ur[l];
        ul[it] = v;
        A[l]      = make_float2(v, 0.0f);
        A[l + Ld] = make_float2(0.0f, 0.0f);
    }
    int nz0 = d_kf_nz[h];
    int nz1 = d_kf_nz[Hd + h];
    if (nz0 | nz1) {
        fft4096<-1>(A, Bf);
        for (int i = threadIdx.x; i < NF; i += 256) Uf[i] = A[i];
        __syncthreads();
    }
    #pragma unroll 1
    for (int c = 0; c < Cd; ++c) {
        int nz = c ? nz1 : nz0;
        float Dch = Dp[c * Hd + h];
        __half* gr = d_g_h + ((size_t)b * CH + (size_t)c * Hd + h) * Ld;
        if (nz) {
            __syncthreads();
            const float2* kfr = d_kf + ((size_t)c * Hd + h) * NF;
            for (int i = threadIdx.x; i < NF; i += 256)
                A[i] = cmulf(Uf[i], kfr[i]);
            fft4096<1>(A, Bf);    // ends with syncthreads; result in A
            #pragma unroll
            for (int it = 0; it < 8; ++it) {
                int l = threadIdx.x + (it << 8);
                float y = A[l].x * (1.0f / (float)NF) + ul[it] * Dch;
                stg[l] = __float2half(0.5f * y * (1.0f + erff(y * 0.70710678118654752f)));
            }
        } else {
            __syncthreads();
            #pragma unroll
            for (int it = 0; it < 8; ++it) {
                int l = threadIdx.x + (it << 8);
                float y = ul[it] * Dch;
                stg[l] = __float2half(0.5f * y * (1.0f + erff(y * 0.70710678118654752f)));
            }
        }
        __syncthreads();
        // vectorized copy: 2048 halves = 4096B, one uint4 per thread
        reinterpret_cast<uint4*>(gr)[threadIdx.x] =
            reinterpret_cast<const uint4*>(stg)[threadIdx.x];
    }
}

// ---------------------------------------------------------------------------
// Kernel 3: W fp32 -> fp16 with GLU-fused row permutation.
// New row r: group = r>>4, w = r&15, h = group*8 + (w&7);
//   w<8  -> orig row h        ("a" half)
//   w>=8 -> orig row h + Hd   (gate half)
// ---------------------------------------------------------------------------
__global__ void whalf_kernel(const float* __restrict__ W) {
    int idx = blockIdx.x * blockDim.x + threadIdx.x;
    if (idx >= OUTD * CH) return;
    int r = idx >> 11;           // / CH
    int k = idx & (CH - 1);
    int grp = r >> 4, w = r & 15;
    int h = grp * 8 + (w & 7);
    int orig = (w < 8) ? h : h + Hd;
    d_W_h[idx] = __float2half(W[(size_t)orig * CH + k]);
}

// ---------------------------------------------------------------------------
// HMMA GEMM helpers
// ---------------------------------------------------------------------------
__device__ __forceinline__ uint32_t smem_u32(const void* p) {
    uint32_t a;
    asm("{ .reg .u64 t; cvta.to.shared.u64 t, %1; cvt.u32.u64 %0, t; }"
        : "=r"(a) : "l"(p));
    return a;
}
#define SWZ128(x) ((x) ^ (((x) >> 3) & 0x70))
__device__ __forceinline__ void cp16(uint32_t dst, const void* src) {
    asm volatile("cp.async.cg.shared.global [%0], [%1], 16;"
                 :: "r"(dst), "l"(src) : "memory");
}
__device__ __forceinline__ void ldsm4(uint32_t* r, uint32_t addr) {
    asm volatile("ldmatrix.sync.aligned.m8n8.x4.shared.b16 {%0,%1,%2,%3}, [%4];"
                 : "=r"(r[0]), "=r"(r[1]), "=r"(r[2]), "=r"(r[3]) : "r"(addr));
}
__device__ __forceinline__ void ldsm4t(uint32_t* r, uint32_t addr) {
    asm volatile("ldmatrix.sync.aligned.m8n8.x4.trans.shared.b16 {%0,%1,%2,%3}, [%4];"
                 : "=r"(r[0]), "=r"(r[1]), "=r"(r[2]), "=r"(r[3]) : "r"(addr));
}
__device__ __forceinline__ void mma16816(float* c, const uint32_t* a,
                                         uint32_t b0, uint32_t b1) {
    asm volatile(
        "mma.sync.aligned.m16n8k16.row.col.f32.f16.f16.f32 "
        "{%0,%1,%2,%3}, {%4,%5,%6,%7}, {%8,%9}, {%0,%1,%2,%3};"
        : "+f"(c[0]), "+f"(c[1]), "+f"(c[2]), "+f"(c[3])
        : "r"(a[0]), "r"(a[1]), "r"(a[2]), "r"(a[3]), "r"(b0), "r"(b1));
}

// Stage: A 128(m)x128B (K-major, SW128) = 16KB ; B 64(k)x512B (l-major) = 32KB
#define STAGE_B   49152
#define B_OFF     16384
#define NSTAGE    3
#define GEMM_SMEM (NSTAGE * STAGE_B)

// B smem phys offset for (k, l): 512B rows, 16B-XOR swizzle within 128B seg
__device__ __forceinline__ uint32_t bswz(int k, int l) {
    return (uint32_t)(k * 512 + ((l >> 6) << 7) + (((l & 63) * 2) ^ ((k & 7) << 4)));
}

__device__ __forceinline__ void load_stage(uint32_t base, int kc, int tid,
                                           const __half* Ap, const __half* Bp) {
    int k0 = kc * 64;
    #pragma unroll
    for (int i = 0; i < 4; ++i) {          // A: 1024 x 16B
        int c = tid + (i << 8);
        int row = c >> 3, col = c & 7;
        cp16(base + SWZ128(row * 128 + col * 16),
             Ap + (size_t)row * CH + k0 + col * 8);
    }
    #pragma unroll
    for (int i = 0; i < 8; ++i) {          // B: 64 rows x 32 chunks of 16B
        int c = tid + (i << 8);
        int row = c >> 5, ch = c & 31;
        cp16(base + B_OFF + bswz(row, ch * 8),
             Bp + (size_t)(k0 + row) * Ld + ch * 8);
    }
    asm volatile("cp.async.commit_group;" ::: "memory");
}

// ---------------------------------------------------------------------------
// Kernel 4: fp16 HMMA GEMM + fused bias/GLU epilogue.
// z-rows interleaved: fragment rows 0-7 = "a", 8-15 = gate for same h.
// out[b][h][l] = (a + ba) * sigmoid(g + bg)
// ---------------------------------------------------------------------------
__global__ void __launch_bounds__(256, 1) gemm_hmma(const float* __restrict__ bias,
                                                    float* __restrict__ out) {
    extern __shared__ char smem[];
    uint32_t sb = smem_u32(smem);
    const int tid = threadIdx.x, lane = tid & 31, wid = tid >> 5;
    const int b  = blockIdx.z;
    const int o0 = blockIdx.y * 128;       // permuted-M tile
    const int l0 = blockIdx.x * 256;
    const int wm = (wid >> 2) * 64;
    const int wn = (wid & 3) * 64;

    const __half* Ap = d_W_h + (size_t)o0 * CH;
    const __half* Bp = d_g_h + (size_t)b * CH * Ld + l0;

    float acc[4][8][4];
    #pragma unroll
    for (int mi = 0; mi < 4; ++mi)
        #pragma unroll
        for (int ni = 0; ni < 8; ++ni)
            #pragma unroll
            for (int v = 0; v < 4; ++v) acc[mi][ni][v] = 0.0f;

    load_stage(sb, 0, tid, Ap, Bp);
    load_stage(sb + STAGE_B, 1, tid, Ap, Bp);
    load_stage(sb + 2 * STAGE_B, 2, tid, Ap, Bp);

    const int arow = (lane & 15);
    const int acol = (lane >> 4) << 4;
    // B ldmatrix.trans lane addressing: k = (lane&7)+(lane&8), n = +((lane&16)>>1)
    const int bk = (lane & 7) + (lane & 8);
    const int bn = (lane & 16) >> 1;

    #pragma unroll 1
    for (int kc = 0; kc < 32; ++kc) {
        uint32_t base = sb + (kc % NSTAGE) * STAGE_B;
        if (kc < 30)       asm volatile("cp.async.wait_group 2;" ::: "memory");
        else if (kc == 30) asm volatile("cp.async.wait_group 1;" ::: "memory");
        else               asm volatile("cp.async.wait_group 0;" ::: "memory");
        __syncthreads();
        #pragma unroll
        for (int ks = 0; ks < 4; ++ks) {
            uint32_t a[4][4], bf[4][4];
            #pragma unroll
            for (int mi = 0; mi < 4; ++mi)
                ldsm4(a[mi], base + SWZ128((wm + mi * 16 + arow) * 128 +
                                           ks * 32 + acol));
            #pragma unroll
            for (int nj = 0; nj < 4; ++nj)
                ldsm4t(bf[nj], base + B_OFF + bswz(ks * 16 + bk,
                                                   wn + nj * 16 + bn));
            #pragma unroll
            for (int mi = 0; mi < 4; ++mi)
                #pragma unroll
                for (int ni = 0; ni < 8; ++ni)
                    mma16816(acc[mi][ni], a[mi],
                             bf[ni >> 1][(ni & 1) * 2],
                             bf[ni >> 1][(ni & 1) * 2 + 1]);
        }
        __syncthreads();
        if (kc + 3 < 32)
            load_stage(base, kc + 3, tid, Ap, Bp);
    }

    // fused epilogue: a=c0,c1 (rows 0-7), gate=c2,c3 (rows 8-15), same h
    #pragma unroll
    for (int mi = 0; mi < 4; ++mi) {
        int g16 = (o0 + wm + mi * 16) >> 4;
        int h = g16 * 8 + (lane >> 2);
        float ba = bias[h];
        float bg = bias[h + Hd];
        float* orow = out + ((size_t)b * Hd + h) * Ld + l0 + wn;
        #pragma unroll
        for (int ni = 0; ni < 8; ++ni) {
            int lc = ni * 8 + (lane & 3) * 2;
            float a0 = acc[mi][ni][0] + ba;
            float a1 = acc[mi][ni][1] + ba;
            float g0 = acc[mi][ni][2] + bg;
            float g1 = acc[mi][ni][3] + bg;
            float2 v = make_float2(a0 / (1.0f + expf(-g0)),
                                   a1 / (1.0f + expf(-g1)));
            *reinterpret_cast<float2*>(orow + lc) = v;
        }
    }
}

// ---------------------------------------------------------------------------
extern "C" void kernel_launch(void* const* d_in, const int* in_sizes, int n_in,
                              void* d_out, int out_size) {
    const float* u    = (const float*)d_in[0];
    const float* kern = (const float*)d_in[1];
    const float* D    = (const float*)d_in[2];
    const float* Wout = (const float*)d_in[3];
    const float* bout = (const float*)d_in[4];
    float* out = (float*)d_out;

    cudaFuncSetAttribute(kf_kernel,
        cudaFuncAttributeMaxDynamicSharedMemorySize, 2 * NF * (int)sizeof(float2));
    cudaFuncSetAttribute(conv_kernel,
        cudaFuncAttributeMaxDynamicSharedMemorySize, 3 * NF * (int)sizeof(float2));
    cudaFuncSetAttribute(gemm_hmma,
        cudaFuncAttributeMaxDynamicSharedMemorySize, GEMM_SMEM);

    kf_kernel<<<CH, 256, 2 * NF * sizeof(float2)>>>(kern);
    conv_kernel<<<Bd * Hd, 256, 3 * NF * sizeof(float2)>>>(u, D);
    whalf_kernel<<<(OUTD * CH + 255) / 256, 256>>>(Wout);
    gemm_hmma<<<dim3(Ld / 256, OUTD / 128, Bd), 256, GEMM_SMEM>>>(bout, out);
}

// round 6
// speedup vs baseline: 8.7561x; 1.0281x over previous
#include <cuda_runtime.h>
#include <cuda_bf16.h>
#include <cuda_fp16.h>
#include <math.h>
#include <stdint.h>

#define Bd   8
#define Hd   1024
#define Ld   2048
#define Cd   2
#define NF   4096      // FFT length = 2L
#define CH   2048      // C*H (GEMM K)
#define OUTD 2048      // 2H  (GEMM M, interleaved a/g rows)

// ---------------- scratch (static device globals; no runtime allocation) ----
__device__ float2 d_kf[(size_t)CH * NF];            // kernel spectra
__device__ int    d_kf_nz[CH];                      // per-row nonzero flags
__device__ __half d_g_h[(size_t)Bd * CH * Ld];      // post-GELU activations fp16 (k-major)
__device__ __half d_W_h[(size_t)OUTD * CH];         // W fp16, rows permuted for fused GLU

__device__ __forceinline__ float2 cmulf(float2 a, float2 b) {
    return make_float2(a.x * b.x - a.y * b.y, a.x * b.y + a.y * b.x);
}

// ---------------------------------------------------------------------------
// Stockham radix-2 FFT, N=4096, 256 threads/block.
// ---------------------------------------------------------------------------
template<int SIGN>
__device__ void fft4096(float2* a, float2* b) {
    float2 *s = a, *d = b;
    int Ns = 1;
    #pragma unroll 1
    for (int stage = 0; stage < 12; ++stage) {
        __syncthreads();
        float wstep = (float)SIGN * 3.14159265358979323846f / (float)Ns;
        #pragma unroll
        for (int it = 0; it < 8; ++it) {
            int j = threadIdx.x + (it << 8);
            float2 v0 = s[j];
            float2 v1 = s[j + 2048];
            int jm = j & (Ns - 1);
            float ang = wstep * (float)jm;
            float sn, cs;
            __sincosf(ang, &sn, &cs);
            float2 t = make_float2(cs * v1.x - sn * v1.y,
                                   cs * v1.y + sn * v1.x);
            int idxD = 2 * j - jm;
            d[idxD]      = make_float2(v0.x + t.x, v0.y + t.y);
            d[idxD + Ns] = make_float2(v0.x - t.x, v0.y - t.y);
        }
        float2* tmp = s; s = d; d = tmp;
        Ns <<= 1;
    }
    __syncthreads();
}

// ---------------------------------------------------------------------------
// Kernel 1: soft-threshold filter rows, FFT nonzero rows.
// ---------------------------------------------------------------------------
__global__ void kf_kernel(const float* __restrict__ kern) {
    extern __shared__ float2 sm[];
    float2* A  = sm;
    float2* Bf = sm + NF;
    int row = blockIdx.x;
    const float* kr = kern + (size_t)row * NF;
    int any = 0;
    for (int i = threadIdx.x; i < NF; i += 256) {
        float v = kr[i];
        float t = fmaxf(fabsf(v) - 0.1f, 0.0f);
        t = copysignf(t, v);
        any |= (t != 0.0f);
        A[i] = make_float2(t, 0.0f);
    }
    int any_nz = __syncthreads_or(any);
    if (!any_nz) {
        if (threadIdx.x == 0) d_kf_nz[row] = 0;
        return;
    }
    fft4096<-1>(A, Bf);
    float2* out = d_kf + (size_t)row * NF;
    for (int i = threadIdx.x; i < NF; i += 256) out[i] = A[i];
    if (threadIdx.x == 0) d_kf_nz[row] = 1;
}

// ---------------------------------------------------------------------------
// Kernel 2: FFT conv (+ collapse for zero rows) + D bypass + GELU -> fp16 d_g_h
// ---------------------------------------------------------------------------
__global__ void conv_kernel(const float* __restrict__ u,
                            const float* __restrict__ Dp) {
    extern __shared__ float2 sm[];
    float2* A  = sm;
    float2* Bf = sm + NF;
    float2* Uf = sm + 2 * NF;
    __half* stg = reinterpret_cast<__half*>(Bf);
    int b = blockIdx.x >> 10;
    int h = blockIdx.x & (Hd - 1);
    const float* ur = u + ((size_t)b * Hd + h) * Ld;
    float ul[8];
    #pragma unroll
    for (int it = 0; it < 8; ++it) {
        int l = threadIdx.x + (it << 8);
        float v = ur[l];
        ul[it] = v;
        A[l]      = make_float2(v, 0.0f);
        A[l + Ld] = make_float2(0.0f, 0.0f);
    }
    int nz0 = d_kf_nz[h];
    int nz1 = d_kf_nz[Hd + h];
    if (nz0 | nz1) {
        fft4096<-1>(A, Bf);
        for (int i = threadIdx.x; i < NF; i += 256) Uf[i] = A[i];
        __syncthreads();
    }
    #pragma unroll 1
    for (int c = 0; c < Cd; ++c) {
        int nz = c ? nz1 : nz0;
        float Dch = Dp[c * Hd + h];
        __half* gr = d_g_h + ((size_t)b * CH + (size_t)c * Hd + h) * Ld;
        if (nz) {
            __syncthreads();
            const float2* kfr = d_kf + ((size_t)c * Hd + h) * NF;
            for (int i = threadIdx.x; i < NF; i += 256)
                A[i] = cmulf(Uf[i], kfr[i]);
            fft4096<1>(A, Bf);
            #pragma unroll
            for (int it = 0; it < 8; ++it) {
                int l = threadIdx.x + (it << 8);
                float y = A[l].x * (1.0f / (float)NF) + ul[it] * Dch;
                stg[l] = __float2half(0.5f * y * (1.0f + erff(y * 0.70710678118654752f)));
            }
        } else {
            __syncthreads();
            #pragma unroll
            for (int it = 0; it < 8; ++it) {
                int l = threadIdx.x + (it << 8);
                float y = ul[it] * Dch;
                stg[l] = __float2half(0.5f * y * (1.0f + erff(y * 0.70710678118654752f)));
            }
        }
        __syncthreads();
        reinterpret_cast<uint4*>(gr)[threadIdx.x] =
            reinterpret_cast<const uint4*>(stg)[threadIdx.x];
    }
}

// ---------------------------------------------------------------------------
// Kernel 3: W fp32 -> fp16 with GLU-fused row permutation.
// ---------------------------------------------------------------------------
__global__ void whalf_kernel(const float* __restrict__ W) {
    int idx = blockIdx.x * blockDim.x + threadIdx.x;
    if (idx >= OUTD * CH) return;
    int r = idx >> 11;
    int k = idx & (CH - 1);
    int grp = r >> 4, w = r & 15;
    int h = grp * 8 + (w & 7);
    int orig = (w < 8) ? h : h + Hd;
    d_W_h[idx] = __float2half(W[(size_t)orig * CH + k]);
}

// ---------------------------------------------------------------------------
// HMMA GEMM helpers
// ---------------------------------------------------------------------------
__device__ __forceinline__ uint32_t smem_u32(const void* p) {
    uint32_t a;
    asm("{ .reg .u64 t; cvta.to.shared.u64 t, %1; cvt.u32.u64 %0, t; }"
        : "=r"(a) : "l"(p));
    return a;
}
#define SWZ128(x) ((x) ^ (((x) >> 3) & 0x70))
__device__ __forceinline__ void cp16(uint32_t dst, const void* src) {
    asm volatile("cp.async.cg.shared.global [%0], [%1], 16;"
                 :: "r"(dst), "l"(src) : "memory");
}
__device__ __forceinline__ void ldsm4(uint32_t* r, uint32_t addr) {
    asm volatile("ldmatrix.sync.aligned.m8n8.x4.shared.b16 {%0,%1,%2,%3}, [%4];"
                 : "=r"(r[0]), "=r"(r[1]), "=r"(r[2]), "=r"(r[3]) : "r"(addr));
}
__device__ __forceinline__ void ldsm4t(uint32_t* r, uint32_t addr) {
    asm volatile("ldmatrix.sync.aligned.m8n8.x4.trans.shared.b16 {%0,%1,%2,%3}, [%4];"
                 : "=r"(r[0]), "=r"(r[1]), "=r"(r[2]), "=r"(r[3]) : "r"(addr));
}
__device__ __forceinline__ void mma16816(float* c, const uint32_t* a,
                                         uint32_t b0, uint32_t b1) {
    asm volatile(
        "mma.sync.aligned.m16n8k16.row.col.f32.f16.f16.f32 "
        "{%0,%1,%2,%3}, {%4,%5,%6,%7}, {%8,%9}, {%0,%1,%2,%3};"
        : "+f"(c[0]), "+f"(c[1]), "+f"(c[2]), "+f"(c[3])
        : "r"(a[0]), "r"(a[1]), "r"(a[2]), "r"(a[3]), "r"(b0), "r"(b1));
}

// Stage: A 128(m)x128B (K-major, SW128) = 16KB ; B 64(k)x512B (l-major) = 32KB
#define STAGE_B   49152
#define B_OFF     16384
#define NSTAGE    4
#define GEMM_SMEM (NSTAGE * STAGE_B)   // 192 KB
#define GTHREADS  512

// B smem phys offset for (k, l): 512B rows, 16B-XOR swizzle within 128B seg
__device__ __forceinline__ uint32_t bswz(int k, int l) {
    return (uint32_t)(k * 512 + ((l >> 6) << 7) + (((l & 63) * 2) ^ ((k & 7) << 4)));
}

__device__ __forceinline__ void load_stage(uint32_t base, int kc, int tid,
                                           const __half* Ap, const __half* Bp) {
    int k0 = kc * 64;
    #pragma unroll
    for (int i = 0; i < 2; ++i) {          // A: 1024 x 16B
        int c = tid + (i << 9);
        int row = c >> 3, col = c & 7;
        cp16(base + SWZ128(row * 128 + col * 16),
             Ap + (size_t)row * CH + k0 + col * 8);
    }
    #pragma unroll
    for (int i = 0; i < 4; ++i) {          // B: 64 rows x 32 chunks of 16B
        int c = tid + (i << 9);
        int row = c >> 5, ch = c & 31;
        cp16(base + B_OFF + bswz(row, ch * 8),
             Bp + (size_t)(k0 + row) * Ld + ch * 8);
    }
    asm volatile("cp.async.commit_group;" ::: "memory");
}

// ---------------------------------------------------------------------------
// Kernel 4: fp16 HMMA GEMM + fused bias/GLU epilogue.
// 512 threads, 16 warps, warp tile 32(m) x 64(n), 4-stage pipeline,
// ONE __syncthreads per K-chunk.
// ---------------------------------------------------------------------------
__global__ void __launch_bounds__(GTHREADS, 1) gemm_hmma(const float* __restrict__ bias,
                                                         float* __restrict__ out) {
    extern __shared__ char smem[];
    uint32_t sb = smem_u32(smem);
    const int tid = threadIdx.x, lane = tid & 31, wid = tid >> 5;
    const int b  = blockIdx.z;
    const int o0 = blockIdx.y * 128;       // permuted-M tile
    const int l0 = blockIdx.x * 256;
    const int wm = (wid >> 2) * 32;        // 4 warp-rows of 32
    const int wn = (wid & 3) * 64;         // 4 warp-cols of 64

    const __half* Ap = d_W_h + (size_t)o0 * CH;
    const __half* Bp = d_g_h + (size_t)b * CH * Ld + l0;

    float acc[2][8][4];
    #pragma unroll
    for (int mi = 0; mi < 2; ++mi)
        #pragma unroll
        for (int ni = 0; ni < 8; ++ni)
            #pragma unroll
            for (int v = 0; v < 4; ++v) acc[mi][ni][v] = 0.0f;

    load_stage(sb, 0, tid, Ap, Bp);
    load_stage(sb + STAGE_B, 1, tid, Ap, Bp);
    load_stage(sb + 2 * STAGE_B, 2, tid, Ap, Bp);

    const int arow = (lane & 15);
    const int acol = (lane >> 4) << 4;
    const int bk = (lane & 7) + (lane & 8);
    const int bn = (lane & 16) >> 1;

    #pragma unroll 1
    for (int kc = 0; kc < 32; ++kc) {
        uint32_t base = sb + (kc & 3) * STAGE_B;
        if (kc <= 29)      asm volatile("cp.async.wait_group 2;" ::: "memory");
        else if (kc == 30) asm volatile("cp.async.wait_group 1;" ::: "memory");
        else               asm volatile("cp.async.wait_group 0;" ::: "memory");
        __syncthreads();
        // prefetch into the stage consumed last iteration (all warps past it)
        if (kc + 3 < 32)
            load_stage(sb + ((kc + 3) & 3) * STAGE_B, kc + 3, tid, Ap, Bp);
        #pragma unroll
        for (int ks = 0; ks < 4; ++ks) {
            uint32_t a[2][4], bf[4][4];
            #pragma unroll
            for (int mi = 0; mi < 2; ++mi)
                ldsm4(a[mi], base + SWZ128((wm + mi * 16 + arow) * 128 +
                                           ks * 32 + acol));
            #pragma unroll
            for (int nj = 0; nj < 4; ++nj)
                ldsm4t(bf[nj], base + B_OFF + bswz(ks * 16 + bk,
                                                   wn + nj * 16 + bn));
            #pragma unroll
            for (int mi = 0; mi < 2; ++mi)
                #pragma unroll
                for (int ni = 0; ni < 8; ++ni)
                    mma16816(acc[mi][ni], a[mi],
                             bf[ni >> 1][(ni & 1) * 2],
                             bf[ni >> 1][(ni & 1) * 2 + 1]);
        }
    }

    // fused epilogue: a=c0,c1 (rows 0-7), gate=c2,c3 (rows 8-15), same h
    #pragma unroll
    for (int mi = 0; mi < 2; ++mi) {
        int g16 = (o0 + wm + mi * 16) >> 4;
        int h = g16 * 8 + (lane >> 2);
        float ba = bias[h];
        float bg = bias[h + Hd];
        float* orow = out + ((size_t)b * Hd + h) * Ld + l0 + wn;
        #pragma unroll
        for (int ni = 0; ni < 8; ++ni) {
            int lc = ni * 8 + (lane & 3) * 2;
            float a0 = acc[mi][ni][0] + ba;
            float a1 = acc[mi][ni][1] + ba;
            float g0 = acc[mi][ni][2] + bg;
            float g1 = acc[mi][ni][3] + bg;
            float2 v = make_float2(a0 / (1.0f + expf(-g0)),
                                   a1 / (1.0f + expf(-g1)));
            *reinterpret_cast<float2*>(orow + lc) = v;
        }
    }
}

// ---------------------------------------------------------------------------
extern "C" void kernel_launch(void* const* d_in, const int* in_sizes, int n_in,
                              void* d_out, int out_size) {
    const float* u    = (const float*)d_in[0];
    const float* kern = (const float*)d_in[1];
    const float* D    = (const float*)d_in[2];
    const float* Wout = (const float*)d_in[3];
    const float* bout = (const float*)d_in[4];
    float* out = (float*)d_out;

    cudaFuncSetAttribute(kf_kernel,
        cudaFuncAttributeMaxDynamicSharedMemorySize, 2 * NF * (int)sizeof(float2));
    cudaFuncSetAttribute(conv_kernel,
        cudaFuncAttributeMaxDynamicSharedMemorySize, 3 * NF * (int)sizeof(float2));
    cudaFuncSetAttribute(gemm_hmma,
        cudaFuncAttributeMaxDynamicSharedMemorySize, GEMM_SMEM);

    kf_kernel<<<CH, 256, 2 * NF * sizeof(float2)>>>(kern);
    conv_kernel<<<Bd * Hd, 256, 3 * NF * sizeof(float2)>>>(u, D);
    whalf_kernel<<<(OUTD * CH + 255) / 256, 256>>>(Wout);
    gemm_hmma<<<dim3(Ld / 256, OUTD / 128, Bd), GTHREADS, GEMM_SMEM>>>(bout, out);
}